// round 11
// baseline (speedup 1.0000x reference)
#include <cuda_runtime.h>
#include <cuda_fp16.h>

// ---------------------------------------------------------------------------
// SSIM3D: two fp32 volumes (4,1,160,160,160), 11-tap separable Gaussian,
// 5 statistics (mu1, mu2, E11, E22, E12), scalar mean output.
//
// R11 = R10 with pass_xy phase-balance + LDS reduction:
//  - stage 1: float2 global loads (22 pairs/row), 4 batched iters
//  - stage 2: 540 units (4x width-5 + 2x width-6 chunks), single iteration,
//    -18% smem traffic
//  - stage 3: exactly 576 units (pair planes 5x16-chunks, e12 8x10-chunks),
//    single iteration
// pass_z unchanged from R10 (measured-good).
// ---------------------------------------------------------------------------

typedef unsigned long long u64t;

namespace {
constexpr int D    = 160;
constexpr int DD   = D * D;                 // 25600
constexpr int NB   = 4;
constexpr long long VOL  = (long long)D * DD;       // 4,096,000
constexpr long long NIMG = (long long)NB * VOL;     // 16,384,000
constexpr int RXA = 42;   // pass_xy region width  (x)
constexpr int RYA = 90;   // pass_xy region height (y)
constexpr int SXA = 43;   // u64 stride, interleaved input tile
constexpr int TSA = 33;   // stride of x-conv planes
constexpr int RZ  = 42;   // pass_z region (z)
constexpr int UZP = 17;   // u64 stride, pass_z tile (x-pairs)
constexpr float C1 = 0.0001f;
constexpr float C2 = 0.0009f;
// pass_xy dynamic smem layout (u64 units)
constexpr int OFF_TM = RYA * SXA;            // 3870
constexpr int OFF_TE = OFF_TM + RYA * TSA;   // 6840
constexpr int OFF_TS = OFF_TE + RYA * TSA;   // 9810
constexpr int SMEM_XY = (OFF_TS + (RYA * TSA + 1) / 2) * 8;   // 90368 B
}

__device__ constexpr float W[11] = {
    0.00102838f, 0.00759876f, 0.03600077f, 0.10936070f, 0.21300554f,
    0.26601173f,
    0.21300554f, 0.10936070f, 0.03600077f, 0.00759876f, 0.00102838f};

// 5 channels x 4 batches x 160^3 halfs = 163.84 MB scratch.
__device__ __half g_mid[5ll * 16384000ll];
__device__ double g_sum;

// ---- packed f32x2 helpers ----
__device__ __forceinline__ u64t pk(float x, float y) {
    u64t r; asm("mov.b64 %0, {%1, %2};" : "=l"(r) : "f"(x), "f"(y)); return r;
}
__device__ __forceinline__ float2 unpk(u64t v) {
    float2 f; asm("mov.b64 {%0, %1}, %2;" : "=f"(f.x), "=f"(f.y) : "l"(v));
    return f;
}
__device__ __forceinline__ u64t fma2(u64t a, u64t w, u64t d) {
    asm("fma.rn.f32x2 %0, %1, %2, %0;" : "+l"(d) : "l"(a), "l"(w));
    return d;
}
__device__ __forceinline__ u64t mul2(u64t a, u64t b) {
    u64t r; asm("mul.rn.f32x2 %0, %1, %2;" : "=l"(r) : "l"(a), "l"(b));
    return r;
}
__device__ __forceinline__ u64t add2(u64t a, u64t b) {
    u64t r; asm("add.rn.f32x2 %0, %1, %2;" : "=l"(r) : "l"(a), "l"(b));
    return r;
}
__device__ __forceinline__ u64t neg2(u64t a) {
    return a ^ 0x8000000080000000ull;
}
// Packed reciprocal: bit-trick seed (no cross-lane borrow: both halves of
// den are positive with bits < 0x7EF311C3) + 3 Newton steps. FMA-pipe only.
__device__ __forceinline__ u64t rcp2(u64t x, u64t two2) {
    u64t r = 0x7EF311C37EF311C3ull - x;
#pragma unroll
    for (int it = 0; it < 3; it++)
        r = mul2(r, add2(two2, neg2(mul2(x, r))));
    return r;
}

// One x-conv unit of WID outputs starting at column xb of `row`.
template <int WID>
__device__ __forceinline__ void xconv_unit(const u64t* __restrict__ sAC,
                                           u64t* __restrict__ tm,
                                           u64t* __restrict__ te,
                                           float* __restrict__ ts,
                                           const u64t* W2, int row, int xb) {
    const int base = row * SXA + xb;
    u64t ac[WID + 10], sq[WID + 10];
    float p12[WID + 10];
#pragma unroll
    for (int j = 0; j < WID + 10; j++) ac[j] = sAC[base + j];
#pragma unroll
    for (int j = 0; j < WID + 10; j++) {
        sq[j] = mul2(ac[j], ac[j]);
        const float2 t = unpk(ac[j]);
        p12[j] = t.x * t.y;
    }
#pragma unroll
    for (int i = 0; i < WID; i++) {
        u64t am = 0ull, ae = 0ull;
        float a12 = 0.f;
#pragma unroll
        for (int k = 0; k < 11; k++) {
            am  = fma2(ac[i + k], W2[k], am);
            ae  = fma2(sq[i + k], W2[k], ae);
            a12 = fmaf(W[k], p12[i + k], a12);
        }
        tm[row * TSA + xb + i] = am;
        te[row * TSA + xb + i] = ae;
        ts[row * TSA + xb + i] = a12;
    }
}

// ---------------------------------------------------------------------------
// Pass A: x-conv then y-conv for one 32(x) x 80(y) tile of one z-slice.
// grid = (10 tiles, 160 z, 4 b), block = 576 threads.
// ---------------------------------------------------------------------------
__global__ void __launch_bounds__(576, 2)
pass_xy(const float* __restrict__ img1, const float* __restrict__ img2) {
    extern __shared__ u64t dsm[];
    u64t* sAC = dsm;                 // (a,c) interleaved input, [90][43]
    u64t* tm  = dsm + OFF_TM;        // (m1,m2)   x-conv plane, [90][33]
    u64t* te  = dsm + OFF_TE;        // (e11,e22) x-conv plane, [90][33]
    float* ts = (float*)(dsm + OFF_TS);   // e12 x-conv plane, [90][33]

    const int tile = blockIdx.x;            // 0..9
    const int x0 = (tile % 5) * 32;
    const int y0 = (tile / 5) * 80;
    const int z  = blockIdx.y;
    const int b  = blockIdx.z;
    const int tid = threadIdx.x;

    if (tile == 0 && z == 0 && b == 0 && tid == 0) g_sum = 0.0;  // fold init

    const float* p1 = img1 + (long long)b * VOL + (long long)z * DD;
    const float* p2 = img2 + (long long)b * VOL + (long long)z * DD;

    // Stage 1: 90 rows x 22 aligned float2 x-pairs (MLP-batched), then
    // interleave (a,c) into sAC. Pair i covers relative cols (2i-1, 2i).
    {
        float2 fa[4], fc[4];
#pragma unroll
        for (int it = 0; it < 4; it++) {
            const int l = tid + it * 576;
            fa[it] = make_float2(0.f, 0.f);
            fc[it] = make_float2(0.f, 0.f);
            if (l < RYA * 22) {
                const int j = l / 22, i = l - j * 22;
                const int gy = y0 - 5 + j;
                const int gx = x0 - 6 + 2 * i;       // even -> 8B aligned
                if (gy >= 0 && gy < D) {
                    if (gx >= 0 && gx + 1 < D) {
                        fa[it] = *(const float2*)(p1 + gy * D + gx);
                        fc[it] = *(const float2*)(p2 + gy * D + gx);
                    } else {
                        if (gx >= 0 && gx < D) {
                            fa[it].x = p1[gy * D + gx];
                            fc[it].x = p2[gy * D + gx];
                        }
                        if (gx + 1 >= 0 && gx + 1 < D) {
                            fa[it].y = p1[gy * D + gx + 1];
                            fc[it].y = p2[gy * D + gx + 1];
                        }
                    }
                }
            }
        }
#pragma unroll
        for (int it = 0; it < 4; it++) {
            const int l = tid + it * 576;
            if (l < RYA * 22) {
                const int j = l / 22, i = l - j * 22;
                const int r0 = 2 * i - 1;
                const int r1 = 2 * i;
                if (r0 >= 0)
                    sAC[j * SXA + r0] = pk(fa[it].x, fc[it].x);
                if (r1 < RXA)
                    sAC[j * SXA + r1] = pk(fa[it].y, fc[it].y);
            }
        }
    }
    __syncthreads();

    u64t W2[11];
#pragma unroll
    for (int k = 0; k < 11; k++) W2[k] = pk(W[k], W[k]);

    // Stage 2: x-conv, 90 rows x 6 chunks (4x5 + 2x6 outputs) = 540 units.
    if (tid < RYA * 6) {
        const int row   = tid % RYA;
        const int chunk = tid / RYA;       // 0..5
        if (chunk < 4)
            xconv_unit<5>(sAC, tm, te, ts, W2, row, chunk * 5);
        else
            xconv_unit<6>(sAC, tm, te, ts, W2, row, 20 + (chunk - 4) * 6);
    }
    __syncthreads();

    // Stage 3: y-conv, exactly 576 units (one iteration).
    //   tid <  320: pair planes (tm/te), 5 chunks of 16 y-outputs
    //   tid >= 320: e12 plane,           8 chunks of 10 y-outputs
    const long long cs = (long long)NB * VOL;
    if (tid < 320) {
        const int g = tid / 160;             // 0: tm, 1: te
        const int r = tid - g * 160;
        const int tx = r & 31;
        const int sub = r >> 5;              // 0..4, chunk of 16
        const u64t* tp = (g == 0) ? tm : te;
        __half* q0 = g_mid + (long long)b * VOL + (long long)z * DD + x0 + tx
                     + (g == 0 ? 0 : 2 * cs);
        __half* q1 = q0 + cs;
        u64t v[26];
#pragma unroll
        for (int j = 0; j < 26; j++)
            v[j] = tp[(sub * 16 + j) * TSA + tx];
#pragma unroll
        for (int i = 0; i < 16; i++) {
            u64t acc = 0ull;
#pragma unroll
            for (int k = 0; k < 11; k++) acc = fma2(v[i + k], W2[k], acc);
            const float2 f = unpk(acc);
            const long long yo = (long long)(y0 + sub * 16 + i) * D;
            q0[yo] = __float2half_rn(f.x);
            q1[yo] = __float2half_rn(f.y);
        }
    } else {
        const int r = tid - 320;             // 0..255
        const int tx = r & 31;
        const int sub = r >> 5;              // 0..7, chunk of 10
        __half* q4 = g_mid + (long long)b * VOL + (long long)z * DD + x0 + tx
                     + 4 * cs;
        float v[20];
#pragma unroll
        for (int j = 0; j < 20; j++)
            v[j] = ts[(sub * 10 + j) * TSA + tx];
#pragma unroll
        for (int i = 0; i < 10; i++) {
            float acc = 0.f;
#pragma unroll
            for (int k = 0; k < 11; k++) acc = fmaf(W[k], v[i + k], acc);
            q4[(long long)(y0 + sub * 10 + i) * D] = __float2half_rn(acc);
        }
    }
}

// ---------------------------------------------------------------------------
// Pass B: z-conv + packed SSIM + reduction, 32(x) x 32(z) tiles.
// grid = (25 tiles [x,z], 160 y, 4 b), block = 128 threads, >=4 blocks/SM.
// (unchanged from R10)
// ---------------------------------------------------------------------------
__global__ void __launch_bounds__(128, 4) pass_z() {
    __shared__ u64t u5[5 * RZ * UZP];   // 28.56 kB
    __shared__ float red[4];

    const int tile = blockIdx.x;
    const int x0 = (tile % 5) * 32;
    const int z0 = (tile / 5) * 32;
    const int y  = blockIdx.y;
    const int b  = blockIdx.z;
    const int tid = threadIdx.x;

    const long long cs = (long long)NB * VOL;
    const __half* basep = g_mid + (long long)b * VOL + (long long)y * D + x0;

    // Fill: 5 channels x 42 z-rows x 4 uint4-chunks (8 halfs each).
    // All 7 loads issued before any store (MLP=7).
    {
        uint4 hv[7];
#pragma unroll
        for (int it = 0; it < 7; it++) {
            const int l = tid + it * 128;
            hv[it] = make_uint4(0u, 0u, 0u, 0u);
            if (l < 5 * RZ * 4) {
                const int ch  = l / (RZ * 4);
                const int rem = l - ch * (RZ * 4);
                const int zz  = rem >> 2;
                const int q   = rem & 3;
                const int gz  = z0 - 5 + zz;
                if (gz >= 0 && gz < D)
                    hv[it] = *(const uint4*)(basep + ch * cs +
                                             (long long)gz * DD + 8 * q);
            }
        }
#pragma unroll
        for (int it = 0; it < 7; it++) {
            const int l = tid + it * 128;
            if (l < 5 * RZ * 4) {
                const int ch  = l / (RZ * 4);
                const int rem = l - ch * (RZ * 4);
                const int zz  = rem >> 2;
                const int q   = rem & 3;
                float2 f;
                u64t* dst = &u5[(ch * RZ + zz) * UZP + 4 * q];
                f = __half22float2(*(const __half2*)&hv[it].x);
                dst[0] = pk(f.x, f.y);
                f = __half22float2(*(const __half2*)&hv[it].y);
                dst[1] = pk(f.x, f.y);
                f = __half22float2(*(const __half2*)&hv[it].z);
                dst[2] = pk(f.x, f.y);
                f = __half22float2(*(const __half2*)&hv[it].w);
                dst[3] = pk(f.x, f.y);
            }
        }
    }
    __syncthreads();

    // Symmetric weights: only W[0..5] needed (W[k] == W[10-k]).
    u64t W2[6];
#pragma unroll
    for (int k = 0; k < 6; k++) W2[k] = pk(W[k], W[k]);

    // Each thread: one x-pair, 4 z-outputs.
    const int xp = tid & 15;
    const int zc = tid >> 4;            // 0..7
    u64t rr[5][4];
#pragma unroll
    for (int ch = 0; ch < 5; ch++) {
        u64t v[14];
#pragma unroll
        for (int j = 0; j < 14; j++)
            v[j] = u5[(ch * RZ + zc * 4 + j) * UZP + xp];
#pragma unroll
        for (int i = 0; i < 4; i++) {
            u64t acc = mul2(v[i + 5], W2[5]);
#pragma unroll
            for (int k = 0; k < 5; k++)
                acc = fma2(add2(v[i + k], v[i + 10 - k]), W2[k], acc);
            rr[ch][i] = acc;
        }
    }

    // Packed SSIM map.
    const u64t two2 = pk(2.f, 2.f);
    const u64t c1p  = pk(C1, C1);
    const u64t c2p  = pk(C2, C2);
    u64t lacc = 0ull;
#pragma unroll
    for (int i = 0; i < 4; i++) {
        const u64t mu1 = rr[0][i], mu2 = rr[1][i];
        const u64t e11 = rr[2][i], e22 = rr[3][i], e12 = rr[4][i];
        const u64t mu1s = mul2(mu1, mu1);
        const u64t mu2s = mul2(mu2, mu2);
        const u64t mu12 = mul2(mu1, mu2);
        const u64t num1 = fma2(mu12, two2, c1p);
        const u64t num2 = fma2(add2(e12, neg2(mu12)), two2, c2p);
        const u64t den1 = add2(add2(mu1s, mu2s), c1p);
        const u64t den2 = add2(add2(add2(e11, neg2(mu1s)),
                                    add2(e22, neg2(mu2s))), c2p);
        lacc = fma2(mul2(num1, num2), rcp2(mul2(den1, den2), two2), lacc);
    }
    const float2 lf = unpk(lacc);
    float lsum = lf.x + lf.y;

    // Block reduction (4 warps).
#pragma unroll
    for (int o = 16; o > 0; o >>= 1)
        lsum += __shfl_xor_sync(0xffffffffu, lsum, o);
    if ((tid & 31) == 0) red[tid >> 5] = lsum;
    __syncthreads();
    if (tid == 0) {
        float s = 0.f;
#pragma unroll
        for (int w = 0; w < 4; w++) s += red[w];
        atomicAdd(&g_sum, (double)s);
    }
}

__global__ void fin_kernel(float* __restrict__ out) {
    out[0] = (float)(g_sum / (double)NIMG);
}

extern "C" void kernel_launch(void* const* d_in, const int* in_sizes, int n_in,
                              void* d_out, int out_size) {
    const float* img1 = (const float*)d_in[0];
    const float* img2 = (const float*)d_in[1];
    (void)in_sizes; (void)n_in; (void)out_size;

    cudaFuncSetAttribute(pass_xy, cudaFuncAttributeMaxDynamicSharedMemorySize,
                         SMEM_XY);

    dim3 grid(10, 160, 4);
    pass_xy<<<grid, 576, SMEM_XY>>>(img1, img2);
    dim3 gridz(25, 160, 4);
    pass_z<<<gridz, 128>>>();
    fin_kernel<<<1, 1>>>((float*)d_out);
}

// round 12
// speedup vs baseline: 1.1480x; 1.1480x over previous
#include <cuda_runtime.h>
#include <cuda_fp16.h>

// ---------------------------------------------------------------------------
// SSIM3D: two fp32 volumes (4,1,160,160,160), 11-tap separable Gaussian,
// scalar mean SSIM output.
//
// R12 = R10 skeleton with the 5->4 channel identity:
//   s = a+c, d = a-c;  conv channels: mu1, mu2, E[s^2], E[d^2]
//   E11+E22 = (Es+Ed)/2,  E12 = (Es-Ed)/4
// All conv chains are packed f32x2 pairs: (mu1,mu2) and (Es,Ed).
// ---------------------------------------------------------------------------

typedef unsigned long long u64t;

namespace {
constexpr int D    = 160;
constexpr int DD   = D * D;                 // 25600
constexpr int NB   = 4;
constexpr long long VOL  = (long long)D * DD;       // 4,096,000
constexpr long long NIMG = (long long)NB * VOL;     // 16,384,000
constexpr int RXA = 42;   // pass_xy region width  (x)
constexpr int RYA = 90;   // pass_xy region height (y)
constexpr int SXA = 43;   // u64 stride, interleaved input tile
constexpr int TSA = 33;   // stride of x-conv planes
constexpr int RZ  = 42;   // pass_z region (z)
constexpr int UZP = 17;   // u64 stride, pass_z tile (x-pairs)
constexpr float C1 = 0.0001f;
constexpr float C2 = 0.0009f;
// pass_xy dynamic smem layout (u64 units): input + 2 pair planes
constexpr int OFF_TM = RYA * SXA;            // 3870
constexpr int OFF_TE = OFF_TM + RYA * TSA;   // 6840
constexpr int SMEM_XY = (OFF_TE + RYA * TSA) * 8;   // 78480 B
}

__device__ constexpr float W[11] = {
    0.00102838f, 0.00759876f, 0.03600077f, 0.10936070f, 0.21300554f,
    0.26601173f,
    0.21300554f, 0.10936070f, 0.03600077f, 0.00759876f, 0.00102838f};

// 4 channels x 4 batches x 160^3 halfs = 131 MB scratch.
__device__ __half g_mid[4ll * 16384000ll];
__device__ double g_sum;

// ---- packed f32x2 helpers ----
__device__ __forceinline__ u64t pk(float x, float y) {
    u64t r; asm("mov.b64 %0, {%1, %2};" : "=l"(r) : "f"(x), "f"(y)); return r;
}
__device__ __forceinline__ float2 unpk(u64t v) {
    float2 f; asm("mov.b64 {%0, %1}, %2;" : "=f"(f.x), "=f"(f.y) : "l"(v));
    return f;
}
__device__ __forceinline__ u64t fma2(u64t a, u64t w, u64t d) {
    asm("fma.rn.f32x2 %0, %1, %2, %0;" : "+l"(d) : "l"(a), "l"(w));
    return d;
}
__device__ __forceinline__ u64t mul2(u64t a, u64t b) {
    u64t r; asm("mul.rn.f32x2 %0, %1, %2;" : "=l"(r) : "l"(a), "l"(b));
    return r;
}
__device__ __forceinline__ u64t add2(u64t a, u64t b) {
    u64t r; asm("add.rn.f32x2 %0, %1, %2;" : "=l"(r) : "l"(a), "l"(b));
    return r;
}
__device__ __forceinline__ u64t neg2(u64t a) {
    return a ^ 0x8000000080000000ull;
}
__device__ __forceinline__ u64t sub2(u64t a, u64t b) { return add2(a, neg2(b)); }
// Packed reciprocal: bit-trick seed + 3 Newton steps (FMA pipe only).
__device__ __forceinline__ u64t rcp2(u64t x, u64t two2) {
    u64t r = 0x7EF311C37EF311C3ull - x;
#pragma unroll
    for (int it = 0; it < 3; it++)
        r = mul2(r, add2(two2, neg2(mul2(x, r))));
    return r;
}

// ---------------------------------------------------------------------------
// Pass A: x-conv then y-conv for one 32(x) x 80(y) tile of one z-slice.
// grid = (10 tiles, 160 z, 4 b), block = 576 threads.
// ---------------------------------------------------------------------------
__global__ void __launch_bounds__(576, 1)
pass_xy(const float* __restrict__ img1, const float* __restrict__ img2) {
    extern __shared__ u64t dsm[];
    u64t* sAC = dsm;                 // (a,c) interleaved input, [90][43]
    u64t* tm  = dsm + OFF_TM;        // (mu1,mu2) x-conv plane, [90][33]
    u64t* te  = dsm + OFF_TE;        // (Es,Ed)   x-conv plane, [90][33]

    const int tile = blockIdx.x;            // 0..9
    const int x0 = (tile % 5) * 32;
    const int y0 = (tile / 5) * 80;
    const int z  = blockIdx.y;
    const int b  = blockIdx.z;
    const int tid = threadIdx.x;

    if (tile == 0 && z == 0 && b == 0 && tid == 0) g_sum = 0.0;  // fold init

    const float* p1 = img1 + (long long)b * VOL + (long long)z * DD;
    const float* p2 = img2 + (long long)b * VOL + (long long)z * DD;

    // Stage 1: prefetch 42x90 halo region (MLP-batched), store interleaved.
    {
        float ra[7], rc[7];
#pragma unroll
        for (int it = 0; it < 7; it++) {
            const int l = tid + it * 576;
            float a = 0.f, c = 0.f;
            if (l < RYA * RXA) {
                const int j = l / RXA, i = l - j * RXA;
                const int gy = y0 - 5 + j;
                const int gx = x0 - 5 + i;
                if (gy >= 0 && gy < D && gx >= 0 && gx < D) {
                    a = p1[gy * D + gx];
                    c = p2[gy * D + gx];
                }
            }
            ra[it] = a; rc[it] = c;
        }
#pragma unroll
        for (int it = 0; it < 7; it++) {
            const int l = tid + it * 576;
            if (l < RYA * RXA)
                sAC[(l / RXA) * SXA + (l % RXA)] = pk(ra[it], rc[it]);
        }
    }
    __syncthreads();

    u64t W2[11];
#pragma unroll
    for (int k = 0; k < 11; k++) W2[k] = pk(W[k], W[k]);

    // Stage 2: x-conv, 90 rows x 8 chunks of 4 outputs = 720 units.
    for (int u = tid; u < RYA * 8; u += 576) {
        const int row   = u % RYA;
        const int chunk = u / RYA;
        const int base = row * SXA + chunk * 4;
        u64t ac[14], sq[14];
#pragma unroll
        for (int j = 0; j < 14; j++) ac[j] = sAC[base + j];
#pragma unroll
        for (int j = 0; j < 14; j++) {
            const float2 t = unpk(ac[j]);
            const u64t sd = pk(t.x + t.y, t.x - t.y);   // (s, d)
            sq[j] = mul2(sd, sd);                        // (s^2, d^2)
        }
#pragma unroll
        for (int i = 0; i < 4; i++) {
            u64t am = 0ull, ae = 0ull;
#pragma unroll
            for (int k = 0; k < 11; k++) {
                am = fma2(ac[i + k], W2[k], am);
                ae = fma2(sq[i + k], W2[k], ae);
            }
            const int x = chunk * 4 + i;
            tm[row * TSA + x] = am;
            te[row * TSA + x] = ae;
        }
    }
    __syncthreads();

    // Stage 3: y-conv, 512 units (2 planes x 32 tx x 8 chunks of 10), 1 iter.
    const long long cs = (long long)NB * VOL;
    if (tid < 512) {
        const int g = tid >> 8;              // 0: mu pair, 1: (Es,Ed) pair
        const int r = tid & 255;
        const int tx = r & 31;
        const int sub = r >> 5;              // 0..7, chunk of 10
        const u64t* tp = (g == 0) ? tm : te;
        __half* q0 = g_mid + (long long)b * VOL + (long long)z * DD + x0 + tx
                     + (g == 0 ? 0 : 2 * cs);
        __half* q1 = q0 + cs;
        u64t v[20];
#pragma unroll
        for (int j = 0; j < 20; j++)
            v[j] = tp[(sub * 10 + j) * TSA + tx];
#pragma unroll
        for (int i = 0; i < 10; i++) {
            u64t acc = 0ull;
#pragma unroll
            for (int k = 0; k < 11; k++) acc = fma2(v[i + k], W2[k], acc);
            const float2 f = unpk(acc);
            const long long yo = (long long)(y0 + sub * 10 + i) * D;
            q0[yo] = __float2half_rn(f.x);
            q1[yo] = __float2half_rn(f.y);
        }
    }
}

// ---------------------------------------------------------------------------
// Pass B: z-conv + packed SSIM + reduction, 32(x) x 32(z) tiles, 4 channels.
// grid = (25 tiles [x,z], 160 y, 4 b), block = 128 threads, >=4 blocks/SM.
// ---------------------------------------------------------------------------
__global__ void __launch_bounds__(128, 4) pass_z() {
    __shared__ u64t u5[4 * RZ * UZP];   // 22.8 kB
    __shared__ float red[4];

    const int tile = blockIdx.x;
    const int x0 = (tile % 5) * 32;
    const int z0 = (tile / 5) * 32;
    const int y  = blockIdx.y;
    const int b  = blockIdx.z;
    const int tid = threadIdx.x;

    const long long cs = (long long)NB * VOL;
    const __half* basep = g_mid + (long long)b * VOL + (long long)y * D + x0;

    // Fill: 4 channels x 42 z-rows x 4 uint4-chunks (8 halfs each).
    // 672 items; all 6 loads issued before any store (MLP=6).
    {
        uint4 hv[6];
#pragma unroll
        for (int it = 0; it < 6; it++) {
            const int l = tid + it * 128;
            hv[it] = make_uint4(0u, 0u, 0u, 0u);
            if (l < 4 * RZ * 4) {
                const int ch  = l / (RZ * 4);
                const int rem = l - ch * (RZ * 4);
                const int zz  = rem >> 2;
                const int q   = rem & 3;
                const int gz  = z0 - 5 + zz;
                if (gz >= 0 && gz < D)
                    hv[it] = *(const uint4*)(basep + ch * cs +
                                             (long long)gz * DD + 8 * q);
            }
        }
#pragma unroll
        for (int it = 0; it < 6; it++) {
            const int l = tid + it * 128;
            if (l < 4 * RZ * 4) {
                const int ch  = l / (RZ * 4);
                const int rem = l - ch * (RZ * 4);
                const int zz  = rem >> 2;
                const int q   = rem & 3;
                float2 f;
                u64t* dst = &u5[(ch * RZ + zz) * UZP + 4 * q];
                f = __half22float2(*(const __half2*)&hv[it].x);
                dst[0] = pk(f.x, f.y);
                f = __half22float2(*(const __half2*)&hv[it].y);
                dst[1] = pk(f.x, f.y);
                f = __half22float2(*(const __half2*)&hv[it].z);
                dst[2] = pk(f.x, f.y);
                f = __half22float2(*(const __half2*)&hv[it].w);
                dst[3] = pk(f.x, f.y);
            }
        }
    }
    __syncthreads();

    // Symmetric weights: only W[0..5] needed (W[k] == W[10-k]).
    u64t W2[6];
#pragma unroll
    for (int k = 0; k < 6; k++) W2[k] = pk(W[k], W[k]);

    // Each thread: one x-pair, 4 z-outputs, 4 channels.
    const int xp = tid & 15;
    const int zc = tid >> 4;            // 0..7
    u64t rr[4][4];
#pragma unroll
    for (int ch = 0; ch < 4; ch++) {
        u64t v[14];
#pragma unroll
        for (int j = 0; j < 14; j++)
            v[j] = u5[(ch * RZ + zc * 4 + j) * UZP + xp];
#pragma unroll
        for (int i = 0; i < 4; i++) {
            u64t acc = mul2(v[i + 5], W2[5]);
#pragma unroll
            for (int k = 0; k < 5; k++)
                acc = fma2(add2(v[i + k], v[i + 10 - k]), W2[k], acc);
            rr[ch][i] = acc;
        }
    }

    // Packed SSIM map from (mu1, mu2, Es, Ed).
    const u64t two2  = pk(2.f, 2.f);
    const u64t half2 = pk(0.5f, 0.5f);
    const u64t quar2 = pk(0.25f, 0.25f);
    const u64t c1p   = pk(C1, C1);
    const u64t c2p   = pk(C2, C2);
    u64t lacc = 0ull;
#pragma unroll
    for (int i = 0; i < 4; i++) {
        const u64t mu1 = rr[0][i], mu2 = rr[1][i];
        const u64t es  = rr[2][i], ed  = rr[3][i];
        const u64t mu1s = mul2(mu1, mu1);
        const u64t mu2s = mul2(mu2, mu2);
        const u64t mu12 = mul2(mu1, mu2);
        const u64t musq = add2(mu1s, mu2s);
        const u64t e12  = mul2(sub2(es, ed), quar2);     // E12
        const u64t ehal = mul2(add2(es, ed), half2);     // E11+E22
        const u64t num1 = fma2(mu12, two2, c1p);
        const u64t num2 = fma2(sub2(e12, mu12), two2, c2p);
        const u64t den1 = add2(musq, c1p);
        const u64t den2 = add2(sub2(ehal, musq), c2p);
        lacc = fma2(mul2(num1, num2), rcp2(mul2(den1, den2), two2), lacc);
    }
    const float2 lf = unpk(lacc);
    float lsum = lf.x + lf.y;

    // Block reduction (4 warps).
#pragma unroll
    for (int o = 16; o > 0; o >>= 1)
        lsum += __shfl_xor_sync(0xffffffffu, lsum, o);
    if ((tid & 31) == 0) red[tid >> 5] = lsum;
    __syncthreads();
    if (tid == 0) {
        float s = 0.f;
#pragma unroll
        for (int w = 0; w < 4; w++) s += red[w];
        atomicAdd(&g_sum, (double)s);
    }
}

__global__ void fin_kernel(float* __restrict__ out) {
    out[0] = (float)(g_sum / (double)NIMG);
}

extern "C" void kernel_launch(void* const* d_in, const int* in_sizes, int n_in,
                              void* d_out, int out_size) {
    const float* img1 = (const float*)d_in[0];
    const float* img2 = (const float*)d_in[1];
    (void)in_sizes; (void)n_in; (void)out_size;

    cudaFuncSetAttribute(pass_xy, cudaFuncAttributeMaxDynamicSharedMemorySize,
                         SMEM_XY);

    dim3 grid(10, 160, 4);
    pass_xy<<<grid, 576, SMEM_XY>>>(img1, img2);
    dim3 gridz(25, 160, 4);
    pass_z<<<gridz, 128>>>();
    fin_kernel<<<1, 1>>>((float*)d_out);
}

// round 13
// speedup vs baseline: 1.1773x; 1.0255x over previous
#include <cuda_runtime.h>
#include <cuda_fp16.h>

// ---------------------------------------------------------------------------
// SSIM3D: two fp32 volumes (4,1,160,160,160), 11-tap separable Gaussian,
// scalar mean SSIM output.
//
// R13 = R12 with the (s,d) transform hoisted to stage 1:
//   s = a+c, d = a-c computed ONCE per input element; conv channels are
//   (ms, md) = conv(s, d) and (Es, Ed) = conv(s^2, d^2).
//   Recovery: 2*mu1*mu2 = (ms^2-md^2)/2, mu1^2+mu2^2 = (ms^2+md^2)/2,
//             2*E12 = (Es-Ed)/2,        E11+E22    = (Es+Ed)/2.
// Stage-2 square prep is now a single mul2 per window element.
// ---------------------------------------------------------------------------

typedef unsigned long long u64t;

namespace {
constexpr int D    = 160;
constexpr int DD   = D * D;                 // 25600
constexpr int NB   = 4;
constexpr long long VOL  = (long long)D * DD;       // 4,096,000
constexpr long long NIMG = (long long)NB * VOL;     // 16,384,000
constexpr int RXA = 42;   // pass_xy region width  (x)
constexpr int RYA = 90;   // pass_xy region height (y)
constexpr int SXA = 43;   // u64 stride, interleaved input tile
constexpr int TSA = 33;   // stride of x-conv planes
constexpr int RZ  = 42;   // pass_z region (z)
constexpr int UZP = 17;   // u64 stride, pass_z tile (x-pairs)
constexpr float C1 = 0.0001f;
constexpr float C2 = 0.0009f;
// pass_xy dynamic smem layout (u64 units): input + 2 pair planes
constexpr int OFF_TM = RYA * SXA;            // 3870
constexpr int OFF_TE = OFF_TM + RYA * TSA;   // 6840
constexpr int SMEM_XY = (OFF_TE + RYA * TSA) * 8;   // 78480 B
}

__device__ constexpr float W[11] = {
    0.00102838f, 0.00759876f, 0.03600077f, 0.10936070f, 0.21300554f,
    0.26601173f,
    0.21300554f, 0.10936070f, 0.03600077f, 0.00759876f, 0.00102838f};

// 4 channels x 4 batches x 160^3 halfs = 131 MB scratch.
__device__ __half g_mid[4ll * 16384000ll];
__device__ double g_sum;

// ---- packed f32x2 helpers ----
__device__ __forceinline__ u64t pk(float x, float y) {
    u64t r; asm("mov.b64 %0, {%1, %2};" : "=l"(r) : "f"(x), "f"(y)); return r;
}
__device__ __forceinline__ float2 unpk(u64t v) {
    float2 f; asm("mov.b64 {%0, %1}, %2;" : "=f"(f.x), "=f"(f.y) : "l"(v));
    return f;
}
__device__ __forceinline__ u64t fma2(u64t a, u64t w, u64t d) {
    asm("fma.rn.f32x2 %0, %1, %2, %0;" : "+l"(d) : "l"(a), "l"(w));
    return d;
}
__device__ __forceinline__ u64t mul2(u64t a, u64t b) {
    u64t r; asm("mul.rn.f32x2 %0, %1, %2;" : "=l"(r) : "l"(a), "l"(b));
    return r;
}
__device__ __forceinline__ u64t add2(u64t a, u64t b) {
    u64t r; asm("add.rn.f32x2 %0, %1, %2;" : "=l"(r) : "l"(a), "l"(b));
    return r;
}
__device__ __forceinline__ u64t neg2(u64t a) {
    return a ^ 0x8000000080000000ull;
}
__device__ __forceinline__ u64t sub2(u64t a, u64t b) { return add2(a, neg2(b)); }
// Packed reciprocal: bit-trick seed + 3 Newton steps (FMA pipe only).
__device__ __forceinline__ u64t rcp2(u64t x, u64t two2) {
    u64t r = 0x7EF311C37EF311C3ull - x;
#pragma unroll
    for (int it = 0; it < 3; it++)
        r = mul2(r, add2(two2, neg2(mul2(x, r))));
    return r;
}

// ---------------------------------------------------------------------------
// Pass A: x-conv then y-conv for one 32(x) x 80(y) tile of one z-slice.
// grid = (10 tiles, 160 z, 4 b), block = 576 threads.
// ---------------------------------------------------------------------------
__global__ void __launch_bounds__(576, 1)
pass_xy(const float* __restrict__ img1, const float* __restrict__ img2) {
    extern __shared__ u64t dsm[];
    u64t* sSD = dsm;                 // (s,d) interleaved input, [90][43]
    u64t* tm  = dsm + OFF_TM;        // (ms,md) x-conv plane, [90][33]
    u64t* te  = dsm + OFF_TE;        // (Es,Ed) x-conv plane, [90][33]

    const int tile = blockIdx.x;            // 0..9
    const int x0 = (tile % 5) * 32;
    const int y0 = (tile / 5) * 80;
    const int z  = blockIdx.y;
    const int b  = blockIdx.z;
    const int tid = threadIdx.x;

    if (tile == 0 && z == 0 && b == 0 && tid == 0) g_sum = 0.0;  // fold init

    const float* p1 = img1 + (long long)b * VOL + (long long)z * DD;
    const float* p2 = img2 + (long long)b * VOL + (long long)z * DD;

    // Stage 1: prefetch 42x90 halo region (MLP-batched), store (s,d) pairs.
    {
        float ra[7], rc[7];
#pragma unroll
        for (int it = 0; it < 7; it++) {
            const int l = tid + it * 576;
            float a = 0.f, c = 0.f;
            if (l < RYA * RXA) {
                const int j = l / RXA, i = l - j * RXA;
                const int gy = y0 - 5 + j;
                const int gx = x0 - 5 + i;
                if (gy >= 0 && gy < D && gx >= 0 && gx < D) {
                    a = p1[gy * D + gx];
                    c = p2[gy * D + gx];
                }
            }
            ra[it] = a; rc[it] = c;
        }
#pragma unroll
        for (int it = 0; it < 7; it++) {
            const int l = tid + it * 576;
            if (l < RYA * RXA)
                sSD[(l / RXA) * SXA + (l % RXA)] =
                    pk(ra[it] + rc[it], ra[it] - rc[it]);
        }
    }
    __syncthreads();

    u64t W2[11];
#pragma unroll
    for (int k = 0; k < 11; k++) W2[k] = pk(W[k], W[k]);

    // Stage 2: x-conv, 90 rows x 8 chunks of 4 outputs = 720 units.
    for (int u = tid; u < RYA * 8; u += 576) {
        const int row   = u % RYA;
        const int chunk = u / RYA;
        const int base = row * SXA + chunk * 4;
        u64t sd[14], sq[14];
#pragma unroll
        for (int j = 0; j < 14; j++) sd[j] = sSD[base + j];
#pragma unroll
        for (int j = 0; j < 14; j++) sq[j] = mul2(sd[j], sd[j]);
#pragma unroll
        for (int i = 0; i < 4; i++) {
            u64t am = 0ull, ae = 0ull;
#pragma unroll
            for (int k = 0; k < 11; k++) {
                am = fma2(sd[i + k], W2[k], am);
                ae = fma2(sq[i + k], W2[k], ae);
            }
            const int x = chunk * 4 + i;
            tm[row * TSA + x] = am;
            te[row * TSA + x] = ae;
        }
    }
    __syncthreads();

    // Stage 3: y-conv, 512 units (2 planes x 32 tx x 8 chunks of 10), 1 iter.
    const long long cs = (long long)NB * VOL;
    if (tid < 512) {
        const int g = tid >> 8;              // 0: (ms,md), 1: (Es,Ed)
        const int r = tid & 255;
        const int tx = r & 31;
        const int sub = r >> 5;              // 0..7, chunk of 10
        const u64t* tp = (g == 0) ? tm : te;
        __half* q0 = g_mid + (long long)b * VOL + (long long)z * DD + x0 + tx
                     + (g == 0 ? 0 : 2 * cs);
        __half* q1 = q0 + cs;
        u64t v[20];
#pragma unroll
        for (int j = 0; j < 20; j++)
            v[j] = tp[(sub * 10 + j) * TSA + tx];
#pragma unroll
        for (int i = 0; i < 10; i++) {
            u64t acc = 0ull;
#pragma unroll
            for (int k = 0; k < 11; k++) acc = fma2(v[i + k], W2[k], acc);
            const float2 f = unpk(acc);
            const long long yo = (long long)(y0 + sub * 10 + i) * D;
            q0[yo] = __float2half_rn(f.x);
            q1[yo] = __float2half_rn(f.y);
        }
    }
}

// ---------------------------------------------------------------------------
// Pass B: z-conv + packed SSIM + reduction, 32(x) x 32(z) tiles, 4 channels.
// grid = (25 tiles [x,z], 160 y, 4 b), block = 128 threads, >=4 blocks/SM.
// ---------------------------------------------------------------------------
__global__ void __launch_bounds__(128, 4) pass_z() {
    __shared__ u64t u5[4 * RZ * UZP];   // 22.8 kB
    __shared__ float red[4];

    const int tile = blockIdx.x;
    const int x0 = (tile % 5) * 32;
    const int z0 = (tile / 5) * 32;
    const int y  = blockIdx.y;
    const int b  = blockIdx.z;
    const int tid = threadIdx.x;

    const long long cs = (long long)NB * VOL;
    const __half* basep = g_mid + (long long)b * VOL + (long long)y * D + x0;

    // Fill: 4 channels x 42 z-rows x 4 uint4-chunks (8 halfs each).
    // 672 items; all 6 loads issued before any store (MLP=6).
    {
        uint4 hv[6];
#pragma unroll
        for (int it = 0; it < 6; it++) {
            const int l = tid + it * 128;
            hv[it] = make_uint4(0u, 0u, 0u, 0u);
            if (l < 4 * RZ * 4) {
                const int ch  = l / (RZ * 4);
                const int rem = l - ch * (RZ * 4);
                const int zz  = rem >> 2;
                const int q   = rem & 3;
                const int gz  = z0 - 5 + zz;
                if (gz >= 0 && gz < D)
                    hv[it] = *(const uint4*)(basep + ch * cs +
                                             (long long)gz * DD + 8 * q);
            }
        }
#pragma unroll
        for (int it = 0; it < 6; it++) {
            const int l = tid + it * 128;
            if (l < 4 * RZ * 4) {
                const int ch  = l / (RZ * 4);
                const int rem = l - ch * (RZ * 4);
                const int zz  = rem >> 2;
                const int q   = rem & 3;
                float2 f;
                u64t* dst = &u5[(ch * RZ + zz) * UZP + 4 * q];
                f = __half22float2(*(const __half2*)&hv[it].x);
                dst[0] = pk(f.x, f.y);
                f = __half22float2(*(const __half2*)&hv[it].y);
                dst[1] = pk(f.x, f.y);
                f = __half22float2(*(const __half2*)&hv[it].z);
                dst[2] = pk(f.x, f.y);
                f = __half22float2(*(const __half2*)&hv[it].w);
                dst[3] = pk(f.x, f.y);
            }
        }
    }
    __syncthreads();

    // Symmetric weights: only W[0..5] needed (W[k] == W[10-k]).
    u64t W2[6];
#pragma unroll
    for (int k = 0; k < 6; k++) W2[k] = pk(W[k], W[k]);

    // Each thread: one x-pair, 4 z-outputs, 4 channels (ms, md, Es, Ed).
    const int xp = tid & 15;
    const int zc = tid >> 4;            // 0..7
    u64t rr[4][4];
#pragma unroll
    for (int ch = 0; ch < 4; ch++) {
        u64t v[14];
#pragma unroll
        for (int j = 0; j < 14; j++)
            v[j] = u5[(ch * RZ + zc * 4 + j) * UZP + xp];
#pragma unroll
        for (int i = 0; i < 4; i++) {
            u64t acc = mul2(v[i + 5], W2[5]);
#pragma unroll
            for (int k = 0; k < 5; k++)
                acc = fma2(add2(v[i + k], v[i + 10 - k]), W2[k], acc);
            rr[ch][i] = acc;
        }
    }

    // Packed SSIM map from (ms, md, Es, Ed):
    //   num1 = (ms^2 - md^2)/2 + C1            (= 2 mu1 mu2 + C1)
    //   den1 = (ms^2 + md^2)/2 + C1            (= mu1^2 + mu2^2 + C1)
    //   num2 = ((Es-Ed) - (ms^2-md^2))/2 + C2  (= 2 sigma12 + C2)
    //   den2 = ((Es+Ed) - (ms^2+md^2))/2 + C2  (= sigma1^2 + sigma2^2 + C2)
    const u64t two2  = pk(2.f, 2.f);
    const u64t half2 = pk(0.5f, 0.5f);
    const u64t c1p   = pk(C1, C1);
    const u64t c2p   = pk(C2, C2);
    u64t lacc = 0ull;
#pragma unroll
    for (int i = 0; i < 4; i++) {
        const u64t ms = rr[0][i], md = rr[1][i];
        const u64t es = rr[2][i], ed = rr[3][i];
        const u64t mssq = mul2(ms, ms);
        const u64t mdsq = mul2(md, md);
        const u64t mdif = sub2(mssq, mdsq);
        const u64t msum = add2(mssq, mdsq);
        const u64t num1 = fma2(mdif, half2, c1p);
        const u64t den1 = fma2(msum, half2, c1p);
        const u64t num2 = fma2(sub2(sub2(es, ed), mdif), half2, c2p);
        const u64t den2 = fma2(sub2(add2(es, ed), msum), half2, c2p);
        lacc = fma2(mul2(num1, num2), rcp2(mul2(den1, den2), two2), lacc);
    }
    const float2 lf = unpk(lacc);
    float lsum = lf.x + lf.y;

    // Block reduction (4 warps).
#pragma unroll
    for (int o = 16; o > 0; o >>= 1)
        lsum += __shfl_xor_sync(0xffffffffu, lsum, o);
    if ((tid & 31) == 0) red[tid >> 5] = lsum;
    __syncthreads();
    if (tid == 0) {
        float s = 0.f;
#pragma unroll
        for (int w = 0; w < 4; w++) s += red[w];
        atomicAdd(&g_sum, (double)s);
    }
}

__global__ void fin_kernel(float* __restrict__ out) {
    out[0] = (float)(g_sum / (double)NIMG);
}

extern "C" void kernel_launch(void* const* d_in, const int* in_sizes, int n_in,
                              void* d_out, int out_size) {
    const float* img1 = (const float*)d_in[0];
    const float* img2 = (const float*)d_in[1];
    (void)in_sizes; (void)n_in; (void)out_size;

    cudaFuncSetAttribute(pass_xy, cudaFuncAttributeMaxDynamicSharedMemorySize,
                         SMEM_XY);

    dim3 grid(10, 160, 4);
    pass_xy<<<grid, 576, SMEM_XY>>>(img1, img2);
    dim3 gridz(25, 160, 4);
    pass_z<<<gridz, 128>>>();
    fin_kernel<<<1, 1>>>((float*)d_out);
}